// round 1
// baseline (speedup 1.0000x reference)
#include <cuda_runtime.h>
#include <cstdint>

// Problem constants (fixed by the dataset):
//   x   [4096, 128]        fp32
//   src [4096, 32768]      fp32
//   tgt [4096, 32768]      fp32
//   f_w [128, 256]         fp32
//   f_b [128]              fp32
//   out [4096, 128]        fp32
#define NN 4096
#define EE 32768
#define DD 128
#define KSPLIT 8
#define KCHUNK (EE / KSPLIT)   // 4096

// Scratch (static __device__ — no runtime allocation)
__device__ float g_u[NN * DD];
__device__ float g_v[NN * DD];
__device__ float g_y[(size_t)EE * DD];
__device__ float g_part[(size_t)KSPLIT * NN * DD];

// ---- packed fp32x2 helpers (Blackwell FFMA2, only reachable via PTX) ----
__device__ __forceinline__ unsigned long long pack_dup(float a) {
    unsigned long long p;
    asm("mov.b64 %0, {%1, %1};" : "=l"(p) : "r"(__float_as_uint(a)));
    return p;
}
__device__ __forceinline__ void ffma2(unsigned long long& d,
                                      unsigned long long a,
                                      unsigned long long b) {
    asm("fma.rn.f32x2 %0, %1, %2, %0;" : "+l"(d) : "l"(a), "l"(b));
}
__device__ __forceinline__ float lo32(unsigned long long v) { return __uint_as_float((unsigned)v); }
__device__ __forceinline__ float hi32(unsigned long long v) { return __uint_as_float((unsigned)(v >> 32)); }

// ============================================================
// Kernel 1: node transform  u = x @ W1^T,  v = x @ W2^T
//   u[n,o] = sum_k x[n,k] * f_w[o, k]
//   v[n,o] = sum_k x[n,k] * f_w[o, 128+k]
// grid = 128 blocks (32 node-rows each), 256 threads:
//   threads 0..127 -> u column o=tid, threads 128..255 -> v column o=tid-128
// ============================================================
__global__ __launch_bounds__(256) void node_transform_kernel(
    const float* __restrict__ x, const float* __restrict__ fw)
{
    __shared__ __align__(16) float xs[32][DD];
    const int tid = threadIdx.x;
    const int n0 = blockIdx.x * 32;

    // load 32 x-rows (4096 floats = 1024 float4)
    #pragma unroll
    for (int l = 0; l < 4; ++l) {
        int idx = tid + l * 256;
        int r = idx >> 5;
        int c = (idx & 31) << 2;
        *(float4*)&xs[r][c] = *(const float4*)&x[(size_t)(n0 + r) * DD + c];
    }
    __syncthreads();

    const int half = tid >> 7;          // 0 -> u, 1 -> v
    const int o    = tid & 127;
    const float* fwrow = fw + (size_t)o * 256 + half * 128;

    float acc[32];
    #pragma unroll
    for (int n = 0; n < 32; ++n) acc[n] = 0.0f;

    #pragma unroll
    for (int kt = 0; kt < DD; kt += 32) {
        float fwreg[32];
        #pragma unroll
        for (int k = 0; k < 32; k += 4) {
            float4 f = *(const float4*)&fwrow[kt + k];
            fwreg[k] = f.x; fwreg[k + 1] = f.y; fwreg[k + 2] = f.z; fwreg[k + 3] = f.w;
        }
        #pragma unroll
        for (int n = 0; n < 32; ++n) {
            #pragma unroll
            for (int k = 0; k < 32; k += 4) {
                float4 xv = *(const float4*)&xs[n][kt + k];   // broadcast within warp
                acc[n] += xv.x * fwreg[k]     + xv.y * fwreg[k + 1]
                        + xv.z * fwreg[k + 2] + xv.w * fwreg[k + 3];
            }
        }
    }

    float* outp = half ? g_v : g_u;
    #pragma unroll
    for (int n = 0; n < 32; ++n)
        outp[(size_t)(n0 + n) * DD + o] = acc[n];
}

// ============================================================
// Kernel 2: fused gather GEMM + bias + relu
//   y[e,o] = relu( sum_n src[n,e]*u[n,o] + sum_n tgt[n,e]*v[n,o] + b[o] )
// M=32768 (e), N=128 (o), K = 4096 per phase, 2 phases.
// Tiles: 128x128, BK=16, 256 threads, 8x8 per thread (fp32x2 packed FMA).
// grid = 256 (e tiles)
// ============================================================
__global__ __launch_bounds__(256) void gather_kernel(
    const float* __restrict__ src, const float* __restrict__ tgt,
    const float* __restrict__ fb)
{
    __shared__ __align__(16) float As[16][128];   // [k][e]
    __shared__ __align__(16) float Bs[16][128];   // [k][o]

    const int tid = threadIdx.x;
    const int tx = tid & 15;        // o-direction
    const int ty = tid >> 4;        // e-direction
    const int e0 = blockIdx.x * 128;

    unsigned long long acc[8][4];
    #pragma unroll
    for (int i = 0; i < 8; ++i)
        #pragma unroll
        for (int j = 0; j < 4; ++j) acc[i][j] = 0ULL;

    #pragma unroll 1
    for (int phase = 0; phase < 2; ++phase) {
        const float* A = phase ? tgt : src;      // A[k,e] = mat[n=k, e]
        const float* B = phase ? g_v : g_u;      // B[k,o]

        #pragma unroll 1
        for (int k0 = 0; k0 < NN; k0 += 16) {
            #pragma unroll
            for (int l = 0; l < 2; ++l) {
                int idx = tid + l * 256;         // 0..511
                int r = idx >> 5;                // 0..15
                int c = (idx & 31) << 2;         // 0..124
                *(float4*)&As[r][c] = *(const float4*)&A[(size_t)(k0 + r) * EE + e0 + c];
                *(float4*)&Bs[r][c] = *(const float4*)&B[(size_t)(k0 + r) * DD + c];
            }
            __syncthreads();

            #pragma unroll
            for (int kk = 0; kk < 16; ++kk) {
                float4 a0 = *(const float4*)&As[kk][ty * 8];
                float4 a1 = *(const float4*)&As[kk][ty * 8 + 4];
                float4 b0 = *(const float4*)&Bs[kk][tx * 8];
                float4 b1 = *(const float4*)&Bs[kk][tx * 8 + 4];
                unsigned long long bb[4];
                { unsigned long long p;
                  asm("mov.b64 %0, {%1, %2};" : "=l"(p) : "r"(__float_as_uint(b0.x)), "r"(__float_as_uint(b0.y))); bb[0] = p;
                  asm("mov.b64 %0, {%1, %2};" : "=l"(p) : "r"(__float_as_uint(b0.z)), "r"(__float_as_uint(b0.w))); bb[1] = p;
                  asm("mov.b64 %0, {%1, %2};" : "=l"(p) : "r"(__float_as_uint(b1.x)), "r"(__float_as_uint(b1.y))); bb[2] = p;
                  asm("mov.b64 %0, {%1, %2};" : "=l"(p) : "r"(__float_as_uint(b1.z)), "r"(__float_as_uint(b1.w))); bb[3] = p;
                }
                float av[8] = {a0.x, a0.y, a0.z, a0.w, a1.x, a1.y, a1.z, a1.w};
                #pragma unroll
                for (int i = 0; i < 8; ++i) {
                    unsigned long long ad = pack_dup(av[i]);
                    ffma2(acc[i][0], ad, bb[0]);
                    ffma2(acc[i][1], ad, bb[1]);
                    ffma2(acc[i][2], ad, bb[2]);
                    ffma2(acc[i][3], ad, bb[3]);
                }
            }
            __syncthreads();
        }
    }

    // epilogue: + bias, relu, store y
    #pragma unroll
    for (int i = 0; i < 8; ++i) {
        int e = e0 + ty * 8 + i;
        #pragma unroll
        for (int j = 0; j < 4; ++j) {
            int o = tx * 8 + j * 2;
            float2 bo = *(const float2*)&fb[o];
            float lo = fmaxf(lo32(acc[i][j]) + bo.x, 0.0f);
            float hi = fmaxf(hi32(acc[i][j]) + bo.y, 0.0f);
            float2 st; st.x = lo; st.y = hi;
            *(float2*)&g_y[(size_t)e * DD + o] = st;
        }
    }
}

// ============================================================
// Kernel 3: scatter GEMM (split-K partials)
//   part[kc][n,o] = sum_{e in chunk kc} tgt[n,e] * y[e,o]
// M=4096 (n), N=128 (o), K=32768 split into 8 chunks of 4096.
// grid = (32, 8): x = n-tile, y = K chunk. Deterministic (no atomics).
// ============================================================
__global__ __launch_bounds__(256) void scatter_kernel(const float* __restrict__ tgt)
{
    __shared__ __align__(16) float As[128][20];   // [m=n][k], padded row (20 floats)
    __shared__ __align__(16) float Bs[16][128];   // [k][o]

    const int tid = threadIdx.x;
    const int tx = tid & 15;
    const int ty = tid >> 4;
    const int n0 = blockIdx.x * 128;
    const int kbase = blockIdx.y * KCHUNK;

    unsigned long long acc[8][4];
    #pragma unroll
    for (int i = 0; i < 8; ++i)
        #pragma unroll
        for (int j = 0; j < 4; ++j) acc[i][j] = 0ULL;

    #pragma unroll 1
    for (int k0 = kbase; k0 < kbase + KCHUNK; k0 += 16) {
        #pragma unroll
        for (int l = 0; l < 2; ++l) {
            int idx = tid + l * 256;          // 0..511
            // A tile: tgt rows are K-contiguous -> store m-major
            int m  = idx >> 2;                // 0..127
            int kq = (idx & 3) << 2;          // 0,4,8,12
            *(float4*)&As[m][kq] = *(const float4*)&tgt[(size_t)(n0 + m) * EE + k0 + kq];
            // B tile: y[k, o]
            int r = idx >> 5;
            int c = (idx & 31) << 2;
            *(float4*)&Bs[r][c] = *(const float4*)&g_y[(size_t)(k0 + r) * DD + c];
        }
        __syncthreads();

        #pragma unroll
        for (int kk = 0; kk < 16; ++kk) {
            float av[8];
            #pragma unroll
            for (int i = 0; i < 8; ++i) av[i] = As[ty * 8 + i][kk];  // warp-broadcast
            float4 b0 = *(const float4*)&Bs[kk][tx * 8];
            float4 b1 = *(const float4*)&Bs[kk][tx * 8 + 4];
            unsigned long long bb[4];
            { unsigned long long p;
              asm("mov.b64 %0, {%1, %2};" : "=l"(p) : "r"(__float_as_uint(b0.x)), "r"(__float_as_uint(b0.y))); bb[0] = p;
              asm("mov.b64 %0, {%1, %2};" : "=l"(p) : "r"(__float_as_uint(b0.z)), "r"(__float_as_uint(b0.w))); bb[1] = p;
              asm("mov.b64 %0, {%1, %2};" : "=l"(p) : "r"(__float_as_uint(b1.x)), "r"(__float_as_uint(b1.y))); bb[2] = p;
              asm("mov.b64 %0, {%1, %2};" : "=l"(p) : "r"(__float_as_uint(b1.z)), "r"(__float_as_uint(b1.w))); bb[3] = p;
            }
            #pragma unroll
            for (int i = 0; i < 8; ++i) {
                unsigned long long ad = pack_dup(av[i]);
                ffma2(acc[i][0], ad, bb[0]);
                ffma2(acc[i][1], ad, bb[1]);
                ffma2(acc[i][2], ad, bb[2]);
                ffma2(acc[i][3], ad, bb[3]);
            }
        }
        __syncthreads();
    }

    float* part = &g_part[(size_t)blockIdx.y * NN * DD];
    #pragma unroll
    for (int i = 0; i < 8; ++i) {
        int n = n0 + ty * 8 + i;
        #pragma unroll
        for (int j = 0; j < 4; ++j) {
            int o = tx * 8 + j * 2;
            float2 st; st.x = lo32(acc[i][j]); st.y = hi32(acc[i][j]);
            *(float2*)&part[(size_t)n * DD + o] = st;
        }
    }
}

// ============================================================
// Kernel 4: reduce split-K partials into d_out (deterministic)
// ============================================================
__global__ __launch_bounds__(256) void reduce_kernel(float* __restrict__ out)
{
    int i = blockIdx.x * blockDim.x + threadIdx.x;   // 0 .. 524287
    float s = 0.0f;
    #pragma unroll
    for (int p = 0; p < KSPLIT; ++p)
        s += g_part[(size_t)p * NN * DD + i];
    out[i] = s;
}

// ============================================================
extern "C" void kernel_launch(void* const* d_in, const int* in_sizes, int n_in,
                              void* d_out, int out_size)
{
    const float* x   = (const float*)d_in[0];
    const float* src = (const float*)d_in[1];
    const float* tgt = (const float*)d_in[2];
    const float* fw  = (const float*)d_in[3];
    const float* fb  = (const float*)d_in[4];
    float* out = (float*)d_out;

    node_transform_kernel<<<NN / 32, 256>>>(x, fw);
    gather_kernel<<<EE / 128, 256>>>(src, tgt, fb);
    scatter_kernel<<<dim3(NN / 128, KSPLIT), 256>>>(tgt);
    reduce_kernel<<<(NN * DD) / 256, 256>>>(out);
}

// round 2
// speedup vs baseline: 1.0011x; 1.0011x over previous
#include <cuda_runtime.h>
#include <cstdint>

// Problem constants (fixed by the dataset):
//   x   [4096, 128]        fp32
//   src [4096, 32768]      fp32
//   tgt [4096, 32768]      fp32
//   f_w [128, 256]         fp32
//   f_b [128]              fp32
//   out [4096, 128]        fp32
#define NN 4096
#define EE 32768
#define DD 128
#define KSPLIT 8
#define KCHUNK (EE / KSPLIT)   // 4096

// Scratch (static __device__ — no runtime allocation)
__device__ float g_u[NN * DD];
__device__ float g_v[NN * DD];
__device__ float g_y[(size_t)EE * DD];
__device__ float g_part[(size_t)KSPLIT * NN * DD];

// ---- packed fp32x2 helpers (Blackwell FFMA2, only reachable via PTX) ----
__device__ __forceinline__ unsigned long long pack_dup(float a) {
    unsigned long long p;
    asm("mov.b64 %0, {%1, %1};" : "=l"(p) : "r"(__float_as_uint(a)));
    return p;
}
__device__ __forceinline__ void ffma2(unsigned long long& d,
                                      unsigned long long a,
                                      unsigned long long b) {
    asm("fma.rn.f32x2 %0, %1, %2, %0;" : "+l"(d) : "l"(a), "l"(b));
}
__device__ __forceinline__ float lo32(unsigned long long v) { return __uint_as_float((unsigned)v); }
__device__ __forceinline__ float hi32(unsigned long long v) { return __uint_as_float((unsigned)(v >> 32)); }

// ============================================================
// Kernel 1: node transform  u = x @ W1^T,  v = x @ W2^T
//   u[n,o] = sum_k x[n,k] * f_w[o, k]
//   v[n,o] = sum_k x[n,k] * f_w[o, 128+k]
// grid = 128 blocks (32 node-rows each), 256 threads:
//   threads 0..127 -> u column o=tid, threads 128..255 -> v column o=tid-128
// ============================================================
__global__ __launch_bounds__(256) void node_transform_kernel(
    const float* __restrict__ x, const float* __restrict__ fw)
{
    __shared__ __align__(16) float xs[32][DD];
    const int tid = threadIdx.x;
    const int n0 = blockIdx.x * 32;

    // load 32 x-rows (4096 floats = 1024 float4)
    #pragma unroll
    for (int l = 0; l < 4; ++l) {
        int idx = tid + l * 256;
        int r = idx >> 5;
        int c = (idx & 31) << 2;
        *(float4*)&xs[r][c] = *(const float4*)&x[(size_t)(n0 + r) * DD + c];
    }
    __syncthreads();

    const int half = tid >> 7;          // 0 -> u, 1 -> v
    const int o    = tid & 127;
    const float* fwrow = fw + (size_t)o * 256 + half * 128;

    float acc[32];
    #pragma unroll
    for (int n = 0; n < 32; ++n) acc[n] = 0.0f;

    #pragma unroll
    for (int kt = 0; kt < DD; kt += 32) {
        float fwreg[32];
        #pragma unroll
        for (int k = 0; k < 32; k += 4) {
            float4 f = *(const float4*)&fwrow[kt + k];
            fwreg[k] = f.x; fwreg[k + 1] = f.y; fwreg[k + 2] = f.z; fwreg[k + 3] = f.w;
        }
        #pragma unroll
        for (int n = 0; n < 32; ++n) {
            #pragma unroll
            for (int k = 0; k < 32; k += 4) {
                float4 xv = *(const float4*)&xs[n][kt + k];   // broadcast within warp
                acc[n] += xv.x * fwreg[k]     + xv.y * fwreg[k + 1]
                        + xv.z * fwreg[k + 2] + xv.w * fwreg[k + 3];
            }
        }
    }

    float* outp = half ? g_v : g_u;
    #pragma unroll
    for (int n = 0; n < 32; ++n)
        outp[(size_t)(n0 + n) * DD + o] = acc[n];
}

// ============================================================
// Kernel 2: fused gather GEMM + bias + relu
//   y[e,o] = relu( sum_n src[n,e]*u[n,o] + sum_n tgt[n,e]*v[n,o] + b[o] )
// M=32768 (e), N=128 (o), K = 4096 per phase, 2 phases.
// Tiles: 128x128, BK=16, 256 threads, 8x8 per thread (fp32x2 packed FMA).
// grid = 256 (e tiles)
// ============================================================
__global__ __launch_bounds__(256) void gather_kernel(
    const float* __restrict__ src, const float* __restrict__ tgt,
    const float* __restrict__ fb)
{
    __shared__ __align__(16) float As[16][128];   // [k][e]
    __shared__ __align__(16) float Bs[16][128];   // [k][o]

    const int tid = threadIdx.x;
    const int tx = tid & 15;        // o-direction
    const int ty = tid >> 4;        // e-direction
    const int e0 = blockIdx.x * 128;

    unsigned long long acc[8][4];
    #pragma unroll
    for (int i = 0; i < 8; ++i)
        #pragma unroll
        for (int j = 0; j < 4; ++j) acc[i][j] = 0ULL;

    #pragma unroll 1
    for (int phase = 0; phase < 2; ++phase) {
        const float* A = phase ? tgt : src;      // A[k,e] = mat[n=k, e]
        const float* B = phase ? g_v : g_u;      // B[k,o]

        #pragma unroll 1
        for (int k0 = 0; k0 < NN; k0 += 16) {
            #pragma unroll
            for (int l = 0; l < 2; ++l) {
                int idx = tid + l * 256;         // 0..511
                int r = idx >> 5;                // 0..15
                int c = (idx & 31) << 2;         // 0..124
                *(float4*)&As[r][c] = *(const float4*)&A[(size_t)(k0 + r) * EE + e0 + c];
                *(float4*)&Bs[r][c] = *(const float4*)&B[(size_t)(k0 + r) * DD + c];
            }
            __syncthreads();

            #pragma unroll
            for (int kk = 0; kk < 16; ++kk) {
                float4 a0 = *(const float4*)&As[kk][ty * 8];
                float4 a1 = *(const float4*)&As[kk][ty * 8 + 4];
                float4 b0 = *(const float4*)&Bs[kk][tx * 8];
                float4 b1 = *(const float4*)&Bs[kk][tx * 8 + 4];
                unsigned long long bb[4];
                { unsigned long long p;
                  asm("mov.b64 %0, {%1, %2};" : "=l"(p) : "r"(__float_as_uint(b0.x)), "r"(__float_as_uint(b0.y))); bb[0] = p;
                  asm("mov.b64 %0, {%1, %2};" : "=l"(p) : "r"(__float_as_uint(b0.z)), "r"(__float_as_uint(b0.w))); bb[1] = p;
                  asm("mov.b64 %0, {%1, %2};" : "=l"(p) : "r"(__float_as_uint(b1.x)), "r"(__float_as_uint(b1.y))); bb[2] = p;
                  asm("mov.b64 %0, {%1, %2};" : "=l"(p) : "r"(__float_as_uint(b1.z)), "r"(__float_as_uint(b1.w))); bb[3] = p;
                }
                float av[8] = {a0.x, a0.y, a0.z, a0.w, a1.x, a1.y, a1.z, a1.w};
                #pragma unroll
                for (int i = 0; i < 8; ++i) {
                    unsigned long long ad = pack_dup(av[i]);
                    ffma2(acc[i][0], ad, bb[0]);
                    ffma2(acc[i][1], ad, bb[1]);
                    ffma2(acc[i][2], ad, bb[2]);
                    ffma2(acc[i][3], ad, bb[3]);
                }
            }
            __syncthreads();
        }
    }

    // epilogue: + bias, relu, store y
    #pragma unroll
    for (int i = 0; i < 8; ++i) {
        int e = e0 + ty * 8 + i;
        #pragma unroll
        for (int j = 0; j < 4; ++j) {
            int o = tx * 8 + j * 2;
            float2 bo = *(const float2*)&fb[o];
            float lo = fmaxf(lo32(acc[i][j]) + bo.x, 0.0f);
            float hi = fmaxf(hi32(acc[i][j]) + bo.y, 0.0f);
            float2 st; st.x = lo; st.y = hi;
            *(float2*)&g_y[(size_t)e * DD + o] = st;
        }
    }
}

// ============================================================
// Kernel 3: scatter GEMM (split-K partials)
//   part[kc][n,o] = sum_{e in chunk kc} tgt[n,e] * y[e,o]
// M=4096 (n), N=128 (o), K=32768 split into 8 chunks of 4096.
// grid = (32, 8): x = n-tile, y = K chunk. Deterministic (no atomics).
// ============================================================
__global__ __launch_bounds__(256) void scatter_kernel(const float* __restrict__ tgt)
{
    __shared__ __align__(16) float As[128][20];   // [m=n][k], padded row (20 floats)
    __shared__ __align__(16) float Bs[16][128];   // [k][o]

    const int tid = threadIdx.x;
    const int tx = tid & 15;
    const int ty = tid >> 4;
    const int n0 = blockIdx.x * 128;
    const int kbase = blockIdx.y * KCHUNK;

    unsigned long long acc[8][4];
    #pragma unroll
    for (int i = 0; i < 8; ++i)
        #pragma unroll
        for (int j = 0; j < 4; ++j) acc[i][j] = 0ULL;

    #pragma unroll 1
    for (int k0 = kbase; k0 < kbase + KCHUNK; k0 += 16) {
        #pragma unroll
        for (int l = 0; l < 2; ++l) {
            int idx = tid + l * 256;          // 0..511
            // A tile: tgt rows are K-contiguous -> store m-major
            int m  = idx >> 2;                // 0..127
            int kq = (idx & 3) << 2;          // 0,4,8,12
            *(float4*)&As[m][kq] = *(const float4*)&tgt[(size_t)(n0 + m) * EE + k0 + kq];
            // B tile: y[k, o]
            int r = idx >> 5;
            int c = (idx & 31) << 2;
            *(float4*)&Bs[r][c] = *(const float4*)&g_y[(size_t)(k0 + r) * DD + c];
        }
        __syncthreads();

        #pragma unroll
        for (int kk = 0; kk < 16; ++kk) {
            float av[8];
            #pragma unroll
            for (int i = 0; i < 8; ++i) av[i] = As[ty * 8 + i][kk];  // warp-broadcast
            float4 b0 = *(const float4*)&Bs[kk][tx * 8];
            float4 b1 = *(const float4*)&Bs[kk][tx * 8 + 4];
            unsigned long long bb[4];
            { unsigned long long p;
              asm("mov.b64 %0, {%1, %2};" : "=l"(p) : "r"(__float_as_uint(b0.x)), "r"(__float_as_uint(b0.y))); bb[0] = p;
              asm("mov.b64 %0, {%1, %2};" : "=l"(p) : "r"(__float_as_uint(b0.z)), "r"(__float_as_uint(b0.w))); bb[1] = p;
              asm("mov.b64 %0, {%1, %2};" : "=l"(p) : "r"(__float_as_uint(b1.x)), "r"(__float_as_uint(b1.y))); bb[2] = p;
              asm("mov.b64 %0, {%1, %2};" : "=l"(p) : "r"(__float_as_uint(b1.z)), "r"(__float_as_uint(b1.w))); bb[3] = p;
            }
            #pragma unroll
            for (int i = 0; i < 8; ++i) {
                unsigned long long ad = pack_dup(av[i]);
                ffma2(acc[i][0], ad, bb[0]);
                ffma2(acc[i][1], ad, bb[1]);
                ffma2(acc[i][2], ad, bb[2]);
                ffma2(acc[i][3], ad, bb[3]);
            }
        }
        __syncthreads();
    }

    float* part = &g_part[(size_t)blockIdx.y * NN * DD];
    #pragma unroll
    for (int i = 0; i < 8; ++i) {
        int n = n0 + ty * 8 + i;
        #pragma unroll
        for (int j = 0; j < 4; ++j) {
            int o = tx * 8 + j * 2;
            float2 st; st.x = lo32(acc[i][j]); st.y = hi32(acc[i][j]);
            *(float2*)&part[(size_t)n * DD + o] = st;
        }
    }
}

// ============================================================
// Kernel 4: reduce split-K partials into d_out (deterministic)
// ============================================================
__global__ __launch_bounds__(256) void reduce_kernel(float* __restrict__ out)
{
    int i = blockIdx.x * blockDim.x + threadIdx.x;   // 0 .. 524287
    float s = 0.0f;
    #pragma unroll
    for (int p = 0; p < KSPLIT; ++p)
        s += g_part[(size_t)p * NN * DD + i];
    out[i] = s;
}

// ============================================================
extern "C" void kernel_launch(void* const* d_in, const int* in_sizes, int n_in,
                              void* d_out, int out_size)
{
    const float* x   = (const float*)d_in[0];
    const float* src = (const float*)d_in[1];
    const float* tgt = (const float*)d_in[2];
    const float* fw  = (const float*)d_in[3];
    const float* fb  = (const float*)d_in[4];
    float* out = (float*)d_out;

    node_transform_kernel<<<NN / 32, 256>>>(x, fw);
    gather_kernel<<<EE / 128, 256>>>(src, tgt, fb);
    scatter_kernel<<<dim3(NN / 128, KSPLIT), 256>>>(tgt);
    reduce_kernel<<<(NN * DD) / 256, 256>>>(out);
}